// round 4
// baseline (speedup 1.0000x reference)
#include <cuda_runtime.h>

// Windowed 3D attention — fp32 with packed f32x2 FMA (Blackwell FFMA2),
// row-pair-interleaved smem layouts, dup'd/transposed weight prep kernel.
// x[1,32,64,128,96], 4x4x4 windows -> 4096 windows, s=64, heads=4, ch=24.
// 512 threads/CTA (16 warps x 4 rows), 100KB dyn smem, 2 CTAs/SM.

#define Hh 64
#define Ww 128
#define Cc 96
#define NWIN 4096

typedef unsigned long long ull;

__device__ float2 dWqkvTd[288 * 96];  // [col][k], dup'd: {w,w}
__device__ float2 dWprojTd[96 * 96];  // [col][k], dup'd

__device__ __forceinline__ ull fma2(ull a, ull b, ull c) {
    ull d;
    asm("fma.rn.f32x2 %0, %1, %2, %3;" : "=l"(d) : "l"(a), "l"(b), "l"(c));
    return d;
}
__device__ __forceinline__ ull mul2(ull a, ull b) {
    ull d;
    asm("mul.rn.f32x2 %0, %1, %2;" : "=l"(d) : "l"(a), "l"(b));
    return d;
}
__device__ __forceinline__ ull dup2(float v) {
    ull d;
    asm("mov.b64 %0, {%1, %1};" : "=l"(d) : "f"(v));
    return d;
}
__device__ __forceinline__ float2 unp2(ull p) {
    float2 r;
    asm("mov.b64 {%0, %1}, %2;" : "=f"(r.x), "=f"(r.y) : "l"(p));
    return r;
}

__global__ void prep_weights(const float* __restrict__ wqkv,
                             const float* __restrict__ wproj) {
    int i = blockIdx.x * blockDim.x + threadIdx.x;
    if (i < 288 * 96) {
        int c = i / 96, k = i % 96;
        float w = wqkv[k * 288 + c];
        dWqkvTd[c * 96 + k] = make_float2(w, w);
    }
    if (i < 96 * 96) {
        int c = i / 96, k = i % 96;
        float w = wproj[k * 96 + c];
        dWprojTd[c * 96 + k] = make_float2(w, w);
    }
}

// smem map (floats):
// [0, 7168)      region A: xsp[32][192] during load+QKV (6144);
//                later scores_p[32][128] @0 (4096) + ktd[24][64]x2 @4096 (3072)
// [7168, 13312)  qsp[32][192]   q paired; per-head attn out written in place
// [13312,19456)  ks[64][96]     row-major
// [19456,25600)  vs[64][96]     row-major
__global__ __launch_bounds__(512, 2)
void win_attn_kernel(const float* __restrict__ x,
                     const float* __restrict__ bproj,
                     float* __restrict__ out) {
    extern __shared__ float sm[];
    float* smA = sm;
    float* qsp = sm + 7168;
    float* ks  = sm + 13312;
    float* vs  = sm + 19456;
    float* scp = sm;           // scores paired
    float* ktd = sm + 4096;    // K^T dup'd: [c][j] float2

    const int tid  = threadIdx.x;
    const int lane = tid & 31;
    const int warp = tid >> 5;        // 0..15
    const int rp0  = warp * 2;        // rowpairs rp0, rp0+1 (rows 4w..4w+3)

    const int wid = blockIdx.x;
    const int d0 = (wid >> 9) * 4, h0 = ((wid >> 5) & 15) * 4, w0 = (wid & 31) * 4;

    // ---- load x, row-pair interleaved: (r,c) -> smA[(r>>1)*192 + 2c + (r&1)] ----
    for (int u = tid; u < 32 * 24; u += 512) {
        int rp = u / 24, c4 = u % 24;
        int r0 = rp * 2, r1 = r0 + 1;
        int wd0 = r0 >> 4, wh0 = (r0 >> 2) & 3, ww0 = r0 & 3;
        int wd1 = r1 >> 4, wh1 = (r1 >> 2) & 3, ww1 = r1 & 3;
        long g0 = ((long)(d0 + wd0) * Hh + (h0 + wh0)) * Ww + (w0 + ww0);
        long g1 = ((long)(d0 + wd1) * Hh + (h0 + wh1)) * Ww + (w0 + ww1);
        float4 e = reinterpret_cast<const float4*>(x + g0 * Cc)[c4];
        float4 o = reinterpret_cast<const float4*>(x + g1 * Cc)[c4];
        float* base = smA + rp * 192 + 8 * c4;
        reinterpret_cast<float4*>(base)[0] = make_float4(e.x, o.x, e.y, o.y);
        reinterpret_cast<float4*>(base)[1] = make_float4(e.z, o.z, e.w, o.w);
    }
    __syncthreads();

    // ---- QKV GEMM: paired rows, dup'd transposed weights ----
    for (int cg = 0; cg < 3; cg++) {
        ull acc[2][3];
        #pragma unroll
        for (int p = 0; p < 2; p++)
            #pragma unroll
            for (int s = 0; s < 3; s++) acc[p][s] = 0ULL;
        const ulonglong2* w0p = reinterpret_cast<const ulonglong2*>(dWqkvTd + (cg * 96 + lane) * 96);
        const ulonglong2* w1p = reinterpret_cast<const ulonglong2*>(dWqkvTd + (cg * 96 + lane + 32) * 96);
        const ulonglong2* w2p = reinterpret_cast<const ulonglong2*>(dWqkvTd + (cg * 96 + lane + 64) * 96);
        const ulonglong2* x0p = reinterpret_cast<const ulonglong2*>(smA + rp0 * 192);
        const ulonglong2* x1p = reinterpret_cast<const ulonglong2*>(smA + (rp0 + 1) * 192);
        #pragma unroll 4
        for (int k2 = 0; k2 < 48; k2++) {
            ulonglong2 xv0 = x0p[k2];
            ulonglong2 xv1 = x1p[k2];
            ulonglong2 wv0 = w0p[k2];
            ulonglong2 wv1 = w1p[k2];
            ulonglong2 wv2 = w2p[k2];
            acc[0][0] = fma2(xv0.x, wv0.x, acc[0][0]); acc[0][0] = fma2(xv0.y, wv0.y, acc[0][0]);
            acc[0][1] = fma2(xv0.x, wv1.x, acc[0][1]); acc[0][1] = fma2(xv0.y, wv1.y, acc[0][1]);
            acc[0][2] = fma2(xv0.x, wv2.x, acc[0][2]); acc[0][2] = fma2(xv0.y, wv2.y, acc[0][2]);
            acc[1][0] = fma2(xv1.x, wv0.x, acc[1][0]); acc[1][0] = fma2(xv1.y, wv0.y, acc[1][0]);
            acc[1][1] = fma2(xv1.x, wv1.x, acc[1][1]); acc[1][1] = fma2(xv1.y, wv1.y, acc[1][1]);
            acc[1][2] = fma2(xv1.x, wv2.x, acc[1][2]); acc[1][2] = fma2(xv1.y, wv2.y, acc[1][2]);
        }
        if (cg == 0) {
            #pragma unroll
            for (int p = 0; p < 2; p++) {
                *reinterpret_cast<ull*>(qsp + (rp0 + p) * 192 + 2 * lane)        = acc[p][0];
                *reinterpret_cast<ull*>(qsp + (rp0 + p) * 192 + 2 * (lane + 32)) = acc[p][1];
                *reinterpret_cast<ull*>(qsp + (rp0 + p) * 192 + 2 * (lane + 64)) = acc[p][2];
            }
        } else {
            float* dst = (cg == 1) ? ks : vs;
            #pragma unroll
            for (int p = 0; p < 2; p++) {
                int re = (rp0 + p) * 2, ro = re + 1;
                float2 f0 = unp2(acc[p][0]), f1 = unp2(acc[p][1]), f2 = unp2(acc[p][2]);
                dst[re * 96 + lane] = f0.x;      dst[ro * 96 + lane] = f0.y;
                dst[re * 96 + lane + 32] = f1.x; dst[ro * 96 + lane + 32] = f1.y;
                dst[re * 96 + lane + 64] = f2.x; dst[ro * 96 + lane + 64] = f2.y;
            }
        }
    }
    __syncthreads();   // qkv ready; smA region A becomes scores_p/ktd

    const float scale = rsqrtf(24.0f);
    const ull scale2 = dup2(scale);

    for (int h = 0; h < 4; h++) {
        const int hc = h * 24;
        // ---- build dup'd K^T for this head ----
        for (int u = tid; u < 24 * 64; u += 512) {
            int c = u >> 6, j = u & 63;
            *reinterpret_cast<ull*>(ktd + 2 * u) = dup2(ks[j * 96 + hc + c]);
        }
        __syncthreads();

        // ---- scores (intra-warp: own 4 rows) ----
        {
            ull a00 = 0, a01 = 0, a10 = 0, a11 = 0;
            #pragma unroll 3
            for (int c2 = 0; c2 < 12; c2++) {
                ulonglong2 q0 = *reinterpret_cast<const ulonglong2*>(qsp + rp0 * 192 + 2 * hc + 4 * c2);
                ulonglong2 q1 = *reinterpret_cast<const ulonglong2*>(qsp + (rp0 + 1) * 192 + 2 * hc + 4 * c2);
                ull k0l = *reinterpret_cast<const ull*>(ktd + 2 * ((2 * c2) * 64 + lane));
                ull k0h = *reinterpret_cast<const ull*>(ktd + 2 * ((2 * c2) * 64 + lane + 32));
                ull k1l = *reinterpret_cast<const ull*>(ktd + 2 * ((2 * c2 + 1) * 64 + lane));
                ull k1h = *reinterpret_cast<const ull*>(ktd + 2 * ((2 * c2 + 1) * 64 + lane + 32));
                a00 = fma2(q0.x, k0l, a00); a00 = fma2(q0.y, k1l, a00);
                a01 = fma2(q0.x, k0h, a01); a01 = fma2(q0.y, k1h, a01);
                a10 = fma2(q1.x, k0l, a10); a10 = fma2(q1.y, k1l, a10);
                a11 = fma2(q1.x, k0h, a11); a11 = fma2(q1.y, k1h, a11);
            }
            *reinterpret_cast<ull*>(scp + rp0 * 128 + 2 * lane)              = mul2(a00, scale2);
            *reinterpret_cast<ull*>(scp + rp0 * 128 + 2 * (lane + 32))       = mul2(a01, scale2);
            *reinterpret_cast<ull*>(scp + (rp0 + 1) * 128 + 2 * lane)        = mul2(a10, scale2);
            *reinterpret_cast<ull*>(scp + (rp0 + 1) * 128 + 2 * (lane + 32)) = mul2(a11, scale2);
        }

        // ---- softmax (own rows; same-thread STS->LDS, no sync needed) ----
        #pragma unroll
        for (int q = 0; q < 4; q++) {
            int rp = rp0 + (q >> 1), par = q & 1;
            float a = scp[rp * 128 + 2 * lane + par];
            float b = scp[rp * 128 + 2 * (lane + 32) + par];
            float m = fmaxf(a, b);
            #pragma unroll
            for (int off = 16; off; off >>= 1)
                m = fmaxf(m, __shfl_xor_sync(0xFFFFFFFFu, m, off));
            float ea = __expf(a - m);
            float eb = __expf(b - m);
            float ssum = ea + eb;
            #pragma unroll
            for (int off = 16; off; off >>= 1)
                ssum += __shfl_xor_sync(0xFFFFFFFFu, ssum, off);
            float inv = 1.0f / ssum;
            scp[rp * 128 + 2 * lane + par] = ea * inv;
            scp[rp * 128 + 2 * (lane + 32) + par] = eb * inv;
        }

        // ---- PV: out(own rows, c=lane<24) into dead q cols of qsp ----
        if (lane < 24) {
            ull o0 = 0, o1 = 0;
            #pragma unroll 4
            for (int j2 = 0; j2 < 32; j2++) {
                ulonglong2 p0 = *reinterpret_cast<const ulonglong2*>(scp + rp0 * 128 + 4 * j2);
                ulonglong2 p1 = *reinterpret_cast<const ulonglong2*>(scp + (rp0 + 1) * 128 + 4 * j2);
                ull vd0 = dup2(vs[(2 * j2) * 96 + hc + lane]);
                ull vd1 = dup2(vs[(2 * j2 + 1) * 96 + hc + lane]);
                o0 = fma2(p0.x, vd0, o0); o0 = fma2(p0.y, vd1, o0);
                o1 = fma2(p1.x, vd0, o1); o1 = fma2(p1.y, vd1, o1);
            }
            *reinterpret_cast<ull*>(qsp + rp0 * 192 + 2 * (hc + lane)) = o0;
            *reinterpret_cast<ull*>(qsp + (rp0 + 1) * 192 + 2 * (hc + lane)) = o1;
        }
        __syncthreads();   // ktd readers done before next head's rebuild
    }

    // ---- proj: paired rows, dup'd transposed weights; scatter to gmem ----
    {
        ull acc[2][3];
        #pragma unroll
        for (int p = 0; p < 2; p++)
            #pragma unroll
            for (int s = 0; s < 3; s++) acc[p][s] = 0ULL;
        const ulonglong2* w0p = reinterpret_cast<const ulonglong2*>(dWprojTd + lane * 96);
        const ulonglong2* w1p = reinterpret_cast<const ulonglong2*>(dWprojTd + (lane + 32) * 96);
        const ulonglong2* w2p = reinterpret_cast<const ulonglong2*>(dWprojTd + (lane + 64) * 96);
        const ulonglong2* x0p = reinterpret_cast<const ulonglong2*>(qsp + rp0 * 192);
        const ulonglong2* x1p = reinterpret_cast<const ulonglong2*>(qsp + (rp0 + 1) * 192);
        #pragma unroll 4
        for (int k2 = 0; k2 < 48; k2++) {
            ulonglong2 xv0 = x0p[k2];
            ulonglong2 xv1 = x1p[k2];
            ulonglong2 wv0 = w0p[k2];
            ulonglong2 wv1 = w1p[k2];
            ulonglong2 wv2 = w2p[k2];
            acc[0][0] = fma2(xv0.x, wv0.x, acc[0][0]); acc[0][0] = fma2(xv0.y, wv0.y, acc[0][0]);
            acc[0][1] = fma2(xv0.x, wv1.x, acc[0][1]); acc[0][1] = fma2(xv0.y, wv1.y, acc[0][1]);
            acc[0][2] = fma2(xv0.x, wv2.x, acc[0][2]); acc[0][2] = fma2(xv0.y, wv2.y, acc[0][2]);
            acc[1][0] = fma2(xv1.x, wv0.x, acc[1][0]); acc[1][0] = fma2(xv1.y, wv0.y, acc[1][0]);
            acc[1][1] = fma2(xv1.x, wv1.x, acc[1][1]); acc[1][1] = fma2(xv1.y, wv1.y, acc[1][1]);
            acc[1][2] = fma2(xv1.x, wv2.x, acc[1][2]); acc[1][2] = fma2(xv1.y, wv2.y, acc[1][2]);
        }
        float b0 = bproj[lane], b1 = bproj[lane + 32], b2 = bproj[lane + 64];
        #pragma unroll
        for (int p = 0; p < 2; p++) {
            float2 f0 = unp2(acc[p][0]), f1 = unp2(acc[p][1]), f2 = unp2(acc[p][2]);
            #pragma unroll
            for (int e = 0; e < 2; e++) {
                int r = (rp0 + p) * 2 + e;
                int wd = r >> 4, wh = (r >> 2) & 3, ww = r & 3;
                long g = ((long)(d0 + wd) * Hh + (h0 + wh)) * Ww + (w0 + ww);
                float* op = out + g * Cc;
                op[lane]      = (e ? f0.y : f0.x) + b0;
                op[lane + 32] = (e ? f1.y : f1.x) + b1;
                op[lane + 64] = (e ? f2.y : f2.x) + b2;
            }
        }
    }
}

extern "C" void kernel_launch(void* const* d_in, const int* in_sizes, int n_in,
                              void* d_out, int out_size) {
    const float* x     = (const float*)d_in[0];
    const float* wqkv  = (const float*)d_in[1];
    const float* wproj = (const float*)d_in[2];
    const float* bproj = (const float*)d_in[3];
    float* out = (float*)d_out;

    prep_weights<<<108, 256>>>(wqkv, wproj);

    cudaFuncSetAttribute(win_attn_kernel,
                         cudaFuncAttributeMaxDynamicSharedMemorySize, 102400);
    win_attn_kernel<<<NWIN, 512, 102400>>>(x, bproj, out);
}